// round 4
// baseline (speedup 1.0000x reference)
#include <cuda_runtime.h>
#include <cuda.h>
#include <cstdint>

#define IN_DIM   5000
#define TOPK     50
#define TOPK_PAD 52      // 4 quarters * 13
#define BATCH    16384
#define H1       32
#define W1STRIDE 36      // padded float stride for float4-friendly rows
#define H2       16
#define OUT_DIM  30

#define ROWS     32      // batch rows per CTA (TMA path)
#define NBIN     4096
#define MAXCAND  1024

// ---- dynamic smem layout for k_mlp_tma (float indices) ----
#define XS_OFF    0                      // 52 slices * 256 floats ([k][row][8])
#define XS_SLICE  (ROWS * 8)             // 256
#define W1_OFF    (52 * XS_SLICE)        // 13312
#define W2_OFF    (W1_OFF + TOPK_PAD * W1STRIDE)   // 13312+1872=15184
#define W3_OFF    (W2_OFF + H1 * H2)                // 15696
#define B1_OFF    (W3_OFF + H2 * OUT_DIM)           // 16176
#define B2_OFF    (B1_OFF + H1)                     // 16208
#define B3_OFF    (B2_OFF + H2)                     // 16224
#define SIDX_OFF  (B3_OFF + 32)                     // 16256 (ints)
#define MBAR_OFF  (SIDX_OFF + 52)                   // 16308 (even -> 8B aligned)
#define SMEM_FLOATS (MBAR_OFF + 2)                  // 16310
#define SMEM_BYTES  (SMEM_FLOATS * 4)               // 65240

// scratch
__device__ int g_topk_idx[64];

static __device__ __forceinline__ unsigned key32(float f) {
    unsigned u = __float_as_uint(f);
    return (u & 0x80000000u) ? ~u : (u | 0x80000000u);
}

static __device__ __forceinline__ uint32_t smem_u32(const void* p) {
    return (uint32_t)__cvta_generic_to_shared(p);
}

// ---------------------------------------------------------------------------
// Kernel 1: single-CTA histogram top-k -> mask + compact index list
// ---------------------------------------------------------------------------
__global__ void __launch_bounds__(1024, 1)
k_topk(const float* __restrict__ logits, float* __restrict__ mask_out) {
    __shared__ unsigned skey[IN_DIM];
    __shared__ int hist[NBIN];
    __shared__ int groupsum[128];
    __shared__ int s_T, s_m, s_ncand;
    __shared__ int      cand_idx[MAXCAND];
    __shared__ unsigned cand_key[MAXCAND];
    __shared__ unsigned char sel[IN_DIM];

    const int tid = threadIdx.x;
    for (int i = tid; i < NBIN; i += 1024) hist[i] = 0;
    if (tid == 0) s_ncand = 0;
    __syncthreads();

    for (int i = tid; i < IN_DIM; i += 1024) {
        unsigned u = key32(logits[i]);
        skey[i] = u;
        atomicAdd(&hist[u >> 20], 1);
    }
    __syncthreads();

    if (tid < 128) {
        int s = 0;
#pragma unroll
        for (int j = 0; j < 32; j++) s += hist[tid * 32 + j];
        groupsum[tid] = s;
    }
    __syncthreads();
    if (tid == 0) {
        int acc = 0, g = 127;
        for (; g > 0; g--) { if (acc + groupsum[g] >= TOPK) break; acc += groupsum[g]; }
        int b = g * 32 + 31;
        for (; b > g * 32; b--) { if (acc + hist[b] >= TOPK) break; acc += hist[b]; }
        s_T = b;  s_m = TOPK - acc;
    }
    __syncthreads();
    const int T = s_T, m = s_m;

    for (int i = tid; i < IN_DIM; i += 1024) {
        const int b = (int)(skey[i] >> 20);
        sel[i] = (b > T) ? 1 : 0;
        if (b == T) {
            int c = atomicAdd(&s_ncand, 1);
            if (c < MAXCAND) { cand_idx[c] = i; cand_key[c] = skey[i]; }
        }
    }
    __syncthreads();

    const int nc = min(s_ncand, MAXCAND);
    for (int ci = tid; ci < nc; ci += 1024) {
        const unsigned ki = cand_key[ci];
        const int      ii = cand_idx[ci];
        int rank = 0;
        for (int cj = 0; cj < nc; cj++) {
            const unsigned kj = cand_key[cj];
            rank += (kj > ki || (kj == ki && cand_idx[cj] < ii)) ? 1 : 0;
        }
        if (rank < m) sel[ii] = 1;
    }
    __syncthreads();

    if (mask_out)
        for (int i = tid; i < IN_DIM; i += 1024)
            mask_out[i] = sel[i] ? 1.0f : 0.0f;

    if (tid < 32) {
        int base = 0;
        for (int c0 = 0; c0 < IN_DIM; c0 += 32) {
            const int i = c0 + tid;
            const bool s = (i < IN_DIM) && sel[i];
            const unsigned b = __ballot_sync(0xffffffffu, s);
            if (s) g_topk_idx[base + __popc(b & ((1u << tid) - 1u))] = i;
            base += __popc(b);
        }
    }
}

// ---------------------------------------------------------------------------
// shared compute body: quad-split MLP given xv[13] already gathered
// ---------------------------------------------------------------------------
static __device__ __forceinline__ void mlp_body(
    const float xv[13], int q, int row,
    const float* __restrict__ sW1,   // [52][W1STRIDE]
    const float* __restrict__ sW2,   // [32][16]
    const float* __restrict__ sW3,   // [16][30]
    const float* __restrict__ sb1, const float* __restrict__ sb2,
    const float* __restrict__ sb3, float* __restrict__ out)
{
    float p[H1];
#pragma unroll
    for (int j = 0; j < H1; j++) p[j] = 0.0f;
#pragma unroll
    for (int i = 0; i < 13; i++) {
        const float v = xv[i];
        const float4* w = (const float4*)(sW1 + (q + 4 * i) * W1STRIDE);
#pragma unroll
        for (int j4 = 0; j4 < 8; j4++) {
            const float4 w4 = w[j4];
            p[4*j4+0] = fmaf(v, w4.x, p[4*j4+0]);
            p[4*j4+1] = fmaf(v, w4.y, p[4*j4+1]);
            p[4*j4+2] = fmaf(v, w4.z, p[4*j4+2]);
            p[4*j4+3] = fmaf(v, w4.w, p[4*j4+3]);
        }
    }

    float a1[H1];
#pragma unroll
    for (int j = 0; j < H1; j++) {
        float s = p[j];
        s += __shfl_xor_sync(0xffffffffu, s, 1);
        s += __shfl_xor_sync(0xffffffffu, s, 2);
        a1[j] = fmaxf(s + sb1[j], 0.0f);
    }

    float a2[H2];
#pragma unroll
    for (int j = 0; j < H2; j++) a2[j] = sb2[j];
#pragma unroll
    for (int i = 0; i < H1; i++) {
        const float v = a1[i];
#pragma unroll
        for (int j = 0; j < H2; j++)
            a2[j] = fmaf(v, sW2[i * H2 + j], a2[j]);
    }
#pragma unroll
    for (int j = 0; j < H2; j++) a2[j] = fmaxf(a2[j], 0.0f);

    float* __restrict__ orow = out + (long)row * OUT_DIM;
    const int j0 = q * 8;
#pragma unroll
    for (int jj = 0; jj < 8; jj++) {
        const int j = j0 + jj;
        if (j < OUT_DIM) {
            float s = sb3[j];
#pragma unroll
            for (int i = 0; i < H2; i++)
                s = fmaf(a2[i], sW3[i * OUT_DIM + j], s);
            orow[j] = s;
        }
    }
}

// weight staging shared by both MLP kernels
static __device__ __forceinline__ void load_weights(
    float* sm, const int* sidx, int tid, int nthr,
    const float* __restrict__ W1, const float* __restrict__ b1,
    const float* __restrict__ W2, const float* __restrict__ b2,
    const float* __restrict__ W3, const float* __restrict__ b3)
{
    for (int t = tid; t < TOPK_PAD * H1; t += nthr) {
        const int k = t >> 5, j = t & 31;
        sm[W1_OFF + k * W1STRIDE + j] = (k < TOPK) ? W1[(long)sidx[k] * H1 + j] : 0.0f;
    }
    for (int t = tid; t < H1 * H2; t += nthr)       sm[W2_OFF + t] = W2[t];
    for (int t = tid; t < H2 * OUT_DIM; t += nthr)  sm[W3_OFF + t] = W3[t];
    if (tid < H1)      sm[B1_OFF + tid] = b1[tid];
    if (tid < H2)      sm[B2_OFF + tid] = b2[tid];
    if (tid < OUT_DIM) sm[B3_OFF + tid] = b3[tid];
}

// ---------------------------------------------------------------------------
// Kernel 2a: TMA gather + MLP. grid = BATCH/ROWS = 512, block = 128.
// ---------------------------------------------------------------------------
__global__ void __launch_bounds__(128, 3)
k_mlp_tma(const __grid_constant__ CUtensorMap tmap,
          const float* __restrict__ W1, const float* __restrict__ b1,
          const float* __restrict__ W2, const float* __restrict__ b2,
          const float* __restrict__ W3, const float* __restrict__ b3,
          float* __restrict__ out) {
    extern __shared__ float sm[];
    int* sidx = (int*)(sm + SIDX_OFF);
    const int tid = threadIdx.x;
    const uint32_t mbar = smem_u32(sm + MBAR_OFF);

    if (tid < TOPK_PAD) sidx[tid] = (tid < TOPK) ? g_topk_idx[tid] : 0;
    if (tid == 0)
        asm volatile("mbarrier.init.shared.b64 [%0], 1;" :: "r"(mbar) : "memory");
    __syncthreads();

    if (tid == 0) {
        asm volatile("mbarrier.arrive.expect_tx.shared.b64 _, [%0], %1;"
                     :: "r"(mbar), "r"((uint32_t)(TOPK_PAD * ROWS * 32)) : "memory");
        const int y0 = blockIdx.x * ROWS;
#pragma unroll 4
        for (int k = 0; k < TOPK_PAD; k++) {
            const int x0 = sidx[k] & ~7;                 // 32B-aligned sector
            const uint32_t dst = smem_u32(sm + XS_OFF + k * XS_SLICE);
            asm volatile(
                "cp.async.bulk.tensor.2d.shared::cta.global.tile.mbarrier::complete_tx::bytes "
                "[%0], [%1, {%2, %3}], [%4];"
                :: "r"(dst), "l"(&tmap), "r"(x0), "r"(y0), "r"(mbar) : "memory");
        }
    }

    // overlap weight staging with TMA flight
    load_weights(sm, sidx, tid, 128, W1, b1, W2, b2, W3, b3);
    __syncthreads();

    // wait for gather
    {
        uint32_t done;
        asm volatile(
            "{.reg .pred p; mbarrier.try_wait.parity.acquire.cta.shared::cta.b64 p, [%1], 0; selp.b32 %0,1,0,p;}"
            : "=r"(done) : "r"(mbar) : "memory");
        while (!done) {
            asm volatile(
                "{.reg .pred p; mbarrier.try_wait.parity.acquire.cta.shared::cta.b64 p, [%1], 0, 0x989680; selp.b32 %0,1,0,p;}"
                : "=r"(done) : "r"(mbar) : "memory");
        }
    }

    const int r = tid >> 2;          // local row 0..31
    const int q = tid & 3;
    const int row = blockIdx.x * ROWS + r;

    float xv[13];
#pragma unroll
    for (int i = 0; i < 13; i++) {
        const int k = q + 4 * i;
        xv[i] = sm[XS_OFF + k * XS_SLICE + r * 8 + (sidx[k] & 7)];
    }

    mlp_body(xv, q, row, sm + W1_OFF, sm + W2_OFF, sm + W3_OFF,
             sm + B1_OFF, sm + B2_OFF, sm + B3_OFF, out);
}

// ---------------------------------------------------------------------------
// Kernel 2b: LDG fallback (if tensormap encode unavailable). grid 512, block 128.
// ---------------------------------------------------------------------------
__global__ void __launch_bounds__(128, 3)
k_mlp_ldg(const float* __restrict__ x,
          const float* __restrict__ W1, const float* __restrict__ b1,
          const float* __restrict__ W2, const float* __restrict__ b2,
          const float* __restrict__ W3, const float* __restrict__ b3,
          float* __restrict__ out) {
    extern __shared__ float sm[];
    int* sidx = (int*)(sm + SIDX_OFF);
    const int tid = threadIdx.x;
    if (tid < TOPK_PAD) sidx[tid] = (tid < TOPK) ? g_topk_idx[tid] : 0;
    __syncthreads();
    load_weights(sm, sidx, tid, 128, W1, b1, W2, b2, W3, b3);
    __syncthreads();

    const int r = tid >> 2, q = tid & 3;
    const int row = blockIdx.x * ROWS + r;
    const float* __restrict__ xr = x + (long)row * IN_DIM;

    float xv[13];
#pragma unroll
    for (int i = 0; i < 13; i++)
        xv[i] = __ldg(xr + sidx[q + 4 * i]);

    mlp_body(xv, q, row, sm + W1_OFF, sm + W2_OFF, sm + W3_OFF,
             sm + B1_OFF, sm + B2_OFF, sm + B3_OFF, out);
}

// ---------------------------------------------------------------------------
typedef CUresult (*EncFn)(CUtensorMap*, CUtensorMapDataType, cuuint32_t, void*,
                          const cuuint64_t*, const cuuint64_t*, const cuuint32_t*,
                          const cuuint32_t*, CUtensorMapInterleave, CUtensorMapSwizzle,
                          CUtensorMapL2promotion, CUtensorMapFloatOOBfill);

extern "C" void kernel_launch(void* const* d_in, const int* in_sizes, int n_in,
                              void* d_out, int out_size) {
    const float* x      = (const float*)d_in[0];
    const float* logits = (const float*)d_in[1];
    const float* W1     = (const float*)d_in[2];
    const float* b1     = (const float*)d_in[3];
    const float* W2     = (const float*)d_in[4];
    const float* b2     = (const float*)d_in[5];
    const float* W3     = (const float*)d_in[6];
    const float* b3     = (const float*)d_in[7];

    float* out  = (float*)d_out;
    float* mask = nullptr;
    if (out_size >= BATCH * OUT_DIM + IN_DIM)
        mask = out + (long)BATCH * OUT_DIM;

    k_topk<<<1, 1024>>>(logits, mask);

    // try TMA path: encode tensormap host-side via cudart entry point
    EncFn enc = nullptr;
    cudaDriverEntryPointQueryResult qres;
    cudaGetDriverEntryPoint("cuTensorMapEncodeTiled", (void**)&enc,
                            cudaEnableDefault, &qres);

    bool tma_ok = false;
    CUtensorMap tmap;
    if (enc) {
        cuuint64_t dims[2]    = {IN_DIM, BATCH};
        cuuint64_t strides[1] = {IN_DIM * sizeof(float)};   // 20000 B
        cuuint32_t box[2]     = {8, ROWS};
        cuuint32_t estr[2]    = {1, 1};
        CUresult r = enc(&tmap, CU_TENSOR_MAP_DATA_TYPE_FLOAT32, 2, (void*)x,
                         dims, strides, box, estr,
                         CU_TENSOR_MAP_INTERLEAVE_NONE, CU_TENSOR_MAP_SWIZZLE_NONE,
                         CU_TENSOR_MAP_L2_PROMOTION_NONE,
                         CU_TENSOR_MAP_FLOAT_OOB_FILL_NONE);
        tma_ok = (r == CUDA_SUCCESS);
    }

    if (tma_ok) {
        static bool attr_set = false;
        if (!attr_set) {
            cudaFuncSetAttribute(k_mlp_tma, cudaFuncAttributeMaxDynamicSharedMemorySize, SMEM_BYTES);
            attr_set = true;
        }
        k_mlp_tma<<<BATCH / ROWS, 128, SMEM_BYTES>>>(tmap, W1, b1, W2, b2, W3, b3, out);
    } else {
        static bool attr_set2 = false;
        if (!attr_set2) {
            cudaFuncSetAttribute(k_mlp_ldg, cudaFuncAttributeMaxDynamicSharedMemorySize, SMEM_BYTES);
            attr_set2 = true;
        }
        k_mlp_ldg<<<BATCH / ROWS, 128, SMEM_BYTES>>>(x, W1, b1, W2, b2, W3, b3, out);
    }
}

// round 5
// speedup vs baseline: 1.2675x; 1.2675x over previous
#include <cuda_runtime.h>
#include <cstdint>

#define IN_DIM   5000
#define TOPK     50
#define BATCH    16384
#define H1       32
#define W1S      36      // padded float stride, 16B-aligned rows for float4
#define H2       16
#define OUT_DIM  30

#define NBIN     4096
#define MAXCAND  512

// scratch (no allocations allowed)
__device__ int g_topk_idx[64];

static __device__ __forceinline__ unsigned key32(float f) {
    unsigned u = __float_as_uint(f);
    return (u & 0x80000000u) ? ~u : (u | 0x80000000u);  // monotonic
}

// ---------------------------------------------------------------------------
// Kernel 1: single-CTA histogram top-k -> mask + compact index list
// grid = 1, block = 1024
// ---------------------------------------------------------------------------
__global__ void __launch_bounds__(1024, 1)
k_topk(const float* __restrict__ logits, float* __restrict__ mask_out) {
    __shared__ unsigned skey[IN_DIM];
    __shared__ int hist[NBIN];
    __shared__ int groupsum[128];
    __shared__ int sgrp[128];           // suffix sums over groups
    __shared__ int sbin[32];            // suffix sums within threshold group
    __shared__ int s_g, s_above, s_T, s_m, s_ncand;
    __shared__ int      cand_idx[MAXCAND];
    __shared__ unsigned cand_key[MAXCAND];
    __shared__ unsigned char sel[IN_DIM];
    __shared__ int wcnt[32], wbase[32];

    const int tid = threadIdx.x;
    const int w = tid >> 5, l = tid & 31;

    for (int i = tid; i < NBIN; i += 1024) hist[i] = 0;
    if (tid == 0) s_ncand = 0;
    __syncthreads();

    // keys + 12-bit histogram
    for (int i = tid; i < IN_DIM; i += 1024) {
        unsigned u = key32(logits[i]);
        skey[i] = u;
        atomicAdd(&hist[u >> 20], 1);
    }
    __syncthreads();

    // group sums (128 groups of 32 bins)
    if (tid < 128) {
        int s = 0;
#pragma unroll
        for (int j = 0; j < 32; j++) s += hist[tid * 32 + j];
        groupsum[tid] = s;
    }
    __syncthreads();
    // parallel suffix sums over groups
    if (tid < 128) {
        int s = 0;
        for (int g = tid; g < 128; g++) s += groupsum[g];
        sgrp[tid] = s;
    }
    __syncthreads();
    // locate threshold group g*: sgrp[g*] >= K > sgrp[g*+1]
    if (tid < 128) {
        const int nxt = (tid == 127) ? 0 : sgrp[tid + 1];
        if (sgrp[tid] >= TOPK && nxt < TOPK) { s_g = tid; s_above = nxt; }
    }
    __syncthreads();
    // suffix within the group
    if (tid < 32) {
        const int b0 = s_g * 32;
        int s = 0;
        for (int b = b0 + tid; b < b0 + 32; b++) s += hist[b];
        sbin[tid] = s;
    }
    __syncthreads();
    if (tid < 32) {
        const int cur = sbin[tid] + s_above;
        const int nxt = (tid == 31) ? s_above : (sbin[tid + 1] + s_above);
        if (cur >= TOPK && nxt < TOPK) { s_T = s_g * 32 + tid; s_m = TOPK - nxt; }
    }
    __syncthreads();
    const int T = s_T, m = s_m;

    // classify; collect threshold-bin candidates
    for (int i = tid; i < IN_DIM; i += 1024) {
        const int b = (int)(skey[i] >> 20);
        sel[i] = (b > T) ? 1 : 0;
        if (b == T) {
            int c = atomicAdd(&s_ncand, 1);
            if (c < MAXCAND) { cand_idx[c] = i; cand_key[c] = skey[i]; }
        }
    }
    __syncthreads();

    // exact rank among candidates (~30 expected); tie -> lower index wins
    const int nc = min(s_ncand, MAXCAND);
    for (int ci = tid; ci < nc; ci += 1024) {
        const unsigned ki = cand_key[ci];
        const int      ii = cand_idx[ci];
        int rank = 0;
        for (int cj = 0; cj < nc; cj++) {
            const unsigned kj = cand_key[cj];
            rank += (kj > ki || (kj == ki && cand_idx[cj] < ii)) ? 1 : 0;
        }
        if (rank < m) sel[ii] = 1;
    }
    __syncthreads();

    // mask output
    if (mask_out)
        for (int i = tid; i < IN_DIM; i += 1024)
            mask_out[i] = sel[i] ? 1.0f : 0.0f;

    // parallel index-ordered compaction: warp w covers [w*160, w*160+160)
    unsigned bm[5];
    int cnt = 0;
#pragma unroll
    for (int c = 0; c < 5; c++) {
        const int i = w * 160 + c * 32 + l;
        const bool s = (i < IN_DIM) && sel[i];
        bm[c] = __ballot_sync(0xffffffffu, s);
        cnt += __popc(bm[c]);
    }
    if (l == 0) wcnt[w] = cnt;
    __syncthreads();
    if (tid < 32) {
        int v = wcnt[tid];
        int inc = v;
#pragma unroll
        for (int d = 1; d < 32; d <<= 1) {
            int t = __shfl_up_sync(0xffffffffu, inc, d);
            if (tid >= d) inc += t;
        }
        wbase[tid] = inc - v;   // exclusive
    }
    __syncthreads();
    int base = wbase[w];
#pragma unroll
    for (int c = 0; c < 5; c++) {
        const int i = w * 160 + c * 32 + l;
        const unsigned b = bm[c];
        if ((i < IN_DIM) && sel[i])
            g_topk_idx[base + __popc(b & ((1u << l) - 1u))] = i;
        base += __popc(b);
    }
}

// ---------------------------------------------------------------------------
// Kernel 2: fused gather + 3-layer MLP. ONE thread per batch row:
//   50 independent gathers batched up-front (per-warp MLP = 50*32 sectors),
//   then 50x32 L1 FMAs from smem (float4), layers 2-3, float2 stores.
// grid = 128, block = 128
// ---------------------------------------------------------------------------
__global__ void __launch_bounds__(128, 1)
k_mlp(const float* __restrict__ x,
      const float* __restrict__ W1, const float* __restrict__ b1,
      const float* __restrict__ W2, const float* __restrict__ b2,
      const float* __restrict__ W3, const float* __restrict__ b3,
      float* __restrict__ out) {
    __shared__ int   sidx[TOPK];
    __shared__ float sW1[TOPK][W1S];
    __shared__ float sW2[H1][H2];
    __shared__ float sW3[H2][OUT_DIM];
    __shared__ float sb1[H1], sb2[H2], sb3[OUT_DIM];

    const int tid = threadIdx.x;
    if (tid < TOPK) sidx[tid] = g_topk_idx[tid];
    __syncthreads();    // sidx visible to all

    const int row = blockIdx.x * 128 + tid;
    const float* __restrict__ xr = x + (long)row * IN_DIM;

    // critical path first: 50 independent scattered gathers (ascending addr)
    float xv[TOPK];
#pragma unroll
    for (int k = 0; k < TOPK; k++)
        xv[k] = __ldg(xr + sidx[k]);

    // weight staging overlaps gather flight (L2-hot after first wave)
    for (int t = tid; t < TOPK * H1; t += 128) {
        const int k = t >> 5, j = t & 31;
        sW1[k][j] = W1[(long)sidx[k] * H1 + j];
    }
    for (int t = tid; t < H1 * H2; t += 128)      sW2[t / H2][t % H2] = W2[t];
    for (int t = tid; t < H2 * OUT_DIM; t += 128) sW3[t / OUT_DIM][t % OUT_DIM] = W3[t];
    if (tid < H1)      sb1[tid] = b1[tid];
    if (tid < H2)      sb2[tid] = b2[tid];
    if (tid < OUT_DIM) sb3[tid] = b3[tid];
    __syncthreads();

    // layer 1 (float4 broadcast reads, 32 independent accumulators)
    float p[H1];
#pragma unroll
    for (int j = 0; j < H1; j++) p[j] = sb1[j];
#pragma unroll
    for (int k = 0; k < TOPK; k++) {
        const float v = xv[k];
        const float4* wrow = (const float4*)&sW1[k][0];
#pragma unroll
        for (int j4 = 0; j4 < 8; j4++) {
            const float4 w4 = wrow[j4];
            p[4*j4+0] = fmaf(v, w4.x, p[4*j4+0]);
            p[4*j4+1] = fmaf(v, w4.y, p[4*j4+1]);
            p[4*j4+2] = fmaf(v, w4.z, p[4*j4+2]);
            p[4*j4+3] = fmaf(v, w4.w, p[4*j4+3]);
        }
    }
#pragma unroll
    for (int j = 0; j < H1; j++) p[j] = fmaxf(p[j], 0.0f);

    // layer 2
    float a2[H2];
#pragma unroll
    for (int j = 0; j < H2; j++) a2[j] = sb2[j];
#pragma unroll
    for (int i = 0; i < H1; i++) {
        const float v = p[i];
#pragma unroll
        for (int j = 0; j < H2; j++)
            a2[j] = fmaf(v, sW2[i][j], a2[j]);
    }
#pragma unroll
    for (int j = 0; j < H2; j++) a2[j] = fmaxf(a2[j], 0.0f);

    // layer 3 -> float2 stores (row base 120B: 8B-aligned)
    float o[OUT_DIM];
#pragma unroll
    for (int j = 0; j < OUT_DIM; j++) {
        float s = sb3[j];
#pragma unroll
        for (int i = 0; i < H2; i++)
            s = fmaf(a2[i], sW3[i][j], s);
        o[j] = s;
    }
    float2* __restrict__ orow = (float2*)(out + (long)row * OUT_DIM);
#pragma unroll
    for (int j = 0; j < OUT_DIM / 2; j++)
        orow[j] = make_float2(o[2*j], o[2*j+1]);
}

// ---------------------------------------------------------------------------
extern "C" void kernel_launch(void* const* d_in, const int* in_sizes, int n_in,
                              void* d_out, int out_size) {
    const float* x      = (const float*)d_in[0];
    const float* logits = (const float*)d_in[1];
    const float* W1     = (const float*)d_in[2];
    const float* b1     = (const float*)d_in[3];
    const float* W2     = (const float*)d_in[4];
    const float* b2     = (const float*)d_in[5];
    const float* W3     = (const float*)d_in[6];
    const float* b3     = (const float*)d_in[7];

    float* out  = (float*)d_out;
    float* mask = nullptr;
    if (out_size >= BATCH * OUT_DIM + IN_DIM)
        mask = out + (long)BATCH * OUT_DIM;   // tuple order: (out, mask)

    k_topk<<<1, 1024>>>(logits, mask);
    k_mlp <<<BATCH / 128, 128>>>(x, W1, b1, W2, b2, W3, b3, out);
}